// round 12
// baseline (speedup 1.0000x reference)
#include <cuda_runtime.h>
#include <cuda_bf16.h>
#include <cstdint>

// out[b,o] = sigmoid( (x@W + colsum(bias))[b,o] / 1024 )
// K1: convert x,W -> bf16 globals + bias colsum eighths (768 small CTAs).
// K2: full-K cp.async 6-stage (wait_group<4>) bf16 MMA GEMM, 128 CTAs,
//     BM=32 BN=64 BK=64, dynamic smem, fused bias+mean+sigmoid epilogue.

#define BATCH   256
#define INDIM   1024
#define OUTDIM  1024

#define BM 32
#define BN 64
#define BK 64
#define NIT (INDIM / BK)          // 16
#define STAGES 6
#define KPARTS 8

#define A_ST 72                   // bf16 units per row (144B, ldmatrix conflict-free)
#define B_ST 72
#define A_STAGE_BYTES (BM * A_ST * 2)              // 4608
#define B_STAGE_BYTES (BK * B_ST * 2)              // 9216
#define STAGE_BYTES   (A_STAGE_BYTES + B_STAGE_BYTES)  // 13824
#define SMEM_TOTAL    (STAGES * STAGE_BYTES)           // 82944

// device-global scratch (no allocation allowed)
__device__ __align__(16) __nv_bfloat16 g_xb[BATCH * INDIM];    // 0.5 MB
__device__ __align__(16) __nv_bfloat16 g_wb[INDIM * OUTDIM];   // 2 MB
__device__ float g_bias_part[KPARTS][OUTDIM];

__device__ __forceinline__ uint32_t pack_bf2(float lo, float hi) {
    __nv_bfloat162 v = __floats2bfloat162_rn(lo, hi);
    return *reinterpret_cast<uint32_t*>(&v);
}
__device__ __forceinline__ void ldmatrix_x4(uint32_t* r, uint32_t addr) {
    asm volatile("ldmatrix.sync.aligned.m8n8.x4.shared.b16 {%0,%1,%2,%3}, [%4];"
                 : "=r"(r[0]), "=r"(r[1]), "=r"(r[2]), "=r"(r[3]) : "r"(addr));
}
__device__ __forceinline__ void ldmatrix_x4_trans(uint32_t* r, uint32_t addr) {
    asm volatile("ldmatrix.sync.aligned.m8n8.x4.trans.shared.b16 {%0,%1,%2,%3}, [%4];"
                 : "=r"(r[0]), "=r"(r[1]), "=r"(r[2]), "=r"(r[3]) : "r"(addr));
}
__device__ __forceinline__ void mma_bf16(float* c, const uint32_t* a, uint32_t b0, uint32_t b1) {
    asm volatile("mma.sync.aligned.m16n8k16.row.col.f32.bf16.bf16.f32 "
                 "{%0,%1,%2,%3}, {%4,%5,%6,%7}, {%8,%9}, {%0,%1,%2,%3};"
                 : "+f"(c[0]), "+f"(c[1]), "+f"(c[2]), "+f"(c[3])
                 : "r"(a[0]), "r"(a[1]), "r"(a[2]), "r"(a[3]), "r"(b0), "r"(b1));
}
__device__ __forceinline__ void cp_async16(uint32_t smem_dst, const void* gptr) {
    asm volatile("cp.async.cg.shared.global [%0], [%1], 16;"
                 :: "r"(smem_dst), "l"(gptr));
}
__device__ __forceinline__ void cp_commit() {
    asm volatile("cp.async.commit_group;");
}
template <int N>
__device__ __forceinline__ void cp_wait() {
    asm volatile("cp.async.wait_group %0;" :: "n"(N));
}
__device__ __forceinline__ float sigmoidf_(float t) {
    return 1.0f / (1.0f + __expf(-t));
}

// ---------------------------------------------------------------------------
// K1: prep. 768 blocks x 256 thr.
//  [0,512):   W f32 -> bf16   (1 uint4 out / thread)
//  [512,640): x f32 -> bf16   (1 uint4 out / thread)
//  [640,768): bias colsum eighths (16 col-blocks x 8 row-parts, 32 rows/thread)
// ---------------------------------------------------------------------------
__global__ void __launch_bounds__(256) prep_kernel(
        const float* __restrict__ x,
        const float* __restrict__ w,
        const float* __restrict__ bias) {
    const int b = blockIdx.x;
    const int tid = threadIdx.x;

    if (b < 512) {                       // W convert
        const float4* s = reinterpret_cast<const float4*>(w);
        uint4* d = reinterpret_cast<uint4*>(g_wb);
        const int o = b * 256 + tid;
        float4 f0 = __ldg(&s[2 * o]);
        float4 f1 = __ldg(&s[2 * o + 1]);
        uint4 u;
        u.x = pack_bf2(f0.x, f0.y); u.y = pack_bf2(f0.z, f0.w);
        u.z = pack_bf2(f1.x, f1.y); u.w = pack_bf2(f1.z, f1.w);
        d[o] = u;
    } else if (b < 640) {                // x convert
        const float4* s = reinterpret_cast<const float4*>(x);
        uint4* d = reinterpret_cast<uint4*>(g_xb);
        const int o = (b - 512) * 256 + tid;
        float4 f0 = __ldg(&s[2 * o]);
        float4 f1 = __ldg(&s[2 * o + 1]);
        uint4 u;
        u.x = pack_bf2(f0.x, f0.y); u.y = pack_bf2(f0.z, f0.w);
        u.z = pack_bf2(f1.x, f1.y); u.w = pack_bf2(f1.z, f1.w);
        d[o] = u;
    } else {                             // bias colsum
        __shared__ float red[4][64];
        const int j      = b - 640;        // 0..127
        const int colblk = j & 15;
        const int rowp   = j >> 4;         // 0..7 (128 rows each)
        const int col    = colblk * 64 + (tid & 63);
        const int rg     = tid >> 6;       // 4 groups x 32 rows
        const float* bp  = bias + (size_t)(rowp * 128 + rg * 32) * OUTDIM + col;
        float s = 0.0f;
        #pragma unroll 16
        for (int r = 0; r < 32; ++r)
            s += __ldg(bp + (size_t)r * OUTDIM);
        red[rg][tid & 63] = s;
        __syncthreads();
        if (tid < 64)
            g_bias_part[rowp][colblk * 64 + tid] =
                red[0][tid] + red[1][tid] + red[2][tid] + red[3][tid];
    }
}

// ---------------------------------------------------------------------------
// K2: GEMM. grid = (16 n, 8 m) = 128 CTAs, 256 thr = 8 warps (2 M x 4 N).
// Warp tile 16x16. BK=64 -> 4 k-steps/iter, NIT=16. 6-stage cp.async.
// ---------------------------------------------------------------------------
__global__ void __launch_bounds__(256) gemm_kernel(float* __restrict__ out) {
    extern __shared__ __align__(16) char smem[];

    const int tid  = threadIdx.x;
    const int lane = tid & 31;
    const int wid  = tid >> 5;
    const int wm   = wid >> 2;     // 0..1 -> 16 rows each
    const int wn   = wid & 3;      // 0..3 -> 16 cols each
    const int m0   = blockIdx.y * BM;
    const int n0   = blockIdx.x * BN;

    // cp.async mapping
    const int a_row = tid >> 3;          // 0..31
    const int a_cc  = tid & 7;           // 0..7 (x8 bf16 = 16B)
    const int b_row = tid >> 3;          // 0..31 (+32 second chunk)
    const int b_cc  = tid & 7;

    const __nv_bfloat16* xa  = g_xb + (size_t)(m0 + a_row) * INDIM + a_cc * 8;
    const __nv_bfloat16* wb0 = g_wb + (size_t)b_row * OUTDIM + n0 + b_cc * 8;
    const __nv_bfloat16* wb1 = wb0 + (size_t)32 * OUTDIM;

    const uint32_t S_base = (uint32_t)__cvta_generic_to_shared(smem);
    const uint32_t a_dst  = S_base + (a_row * A_ST + a_cc * 8) * 2;
    const uint32_t b_dst0 = S_base + A_STAGE_BYTES + (b_row * B_ST + b_cc * 8) * 2;
    const uint32_t b_dst1 = S_base + A_STAGE_BYTES + ((b_row + 32) * B_ST + b_cc * 8) * 2;

    // fragment offsets within one stage (bytes); k-step s in 0..3
    const int lr = lane & 15;
    const int lc = (lane >> 4) << 3;
    uint32_t a_off[4], b_off[4];
    #pragma unroll
    for (int s = 0; s < 4; ++s) {
        a_off[s] = ((wm * 16 + lr) * A_ST + s * 16 + lc) * 2;
        b_off[s] = (uint32_t)A_STAGE_BYTES + ((s * 16 + lr) * B_ST + wn * 16 + lc) * 2;
    }

    float acc[2][4];
    #pragma unroll
    for (int i = 0; i < 2; ++i)
        #pragma unroll
        for (int c = 0; c < 4; ++c)
            acc[i][c] = 0.0f;

    // prologue: fill STAGES-1 = 5 stages
    #pragma unroll
    for (int s = 0; s < STAGES - 1; ++s) {
        const uint32_t so = s * STAGE_BYTES;
        cp_async16(a_dst  + so, xa  + s * BK);
        cp_async16(b_dst0 + so, wb0 + (size_t)s * BK * OUTDIM);
        cp_async16(b_dst1 + so, wb1 + (size_t)s * BK * OUTDIM);
        cp_commit();
    }

    #pragma unroll
    for (int it = 0; it < NIT; ++it) {
        cp_wait<STAGES - 2>();
        __syncthreads();

        // issue next stage FIRST (max lead time); safe: barrier above proves
        // every warp finished reading buffer (it-1)%STAGES last iteration.
        const int nk = it + STAGES - 1;
        if (nk < NIT) {
            const uint32_t so = (nk % STAGES) * STAGE_BYTES;
            cp_async16(a_dst  + so, xa  + nk * BK);
            cp_async16(b_dst0 + so, wb0 + (size_t)nk * BK * OUTDIM);
            cp_async16(b_dst1 + so, wb1 + (size_t)nk * BK * OUTDIM);
        }
        cp_commit();

        const uint32_t Sb = (it % STAGES) * STAGE_BYTES;
        #pragma unroll
        for (int s = 0; s < 4; ++s) {
            uint32_t af[4], bf[4];
            ldmatrix_x4(af, S_base + Sb + a_off[s]);
            ldmatrix_x4_trans(bf, S_base + Sb + b_off[s]);
            mma_bf16(acc[0], af, bf[0], bf[1]);
            mma_bf16(acc[1], af, bf[2], bf[3]);
        }
    }

    // fused epilogue: bias mean + sigmoid
    const float inv = 1.0f / (float)INDIM;
    const int crow = lane >> 2;
    const int ccol = (lane & 3) << 1;

    #pragma unroll
    for (int nt = 0; nt < 2; ++nt) {
        const int col = n0 + wn * 16 + nt * 8 + ccol;
        float bs0 = 0.0f, bs1 = 0.0f;
        #pragma unroll
        for (int k = 0; k < KPARTS; ++k) {
            bs0 += g_bias_part[k][col];
            bs1 += g_bias_part[k][col + 1];
        }
        const int row0 = m0 + wm * 16 + crow;
        float2 r0 = make_float2(sigmoidf_((acc[nt][0] + bs0) * inv),
                                sigmoidf_((acc[nt][1] + bs1) * inv));
        float2 r1 = make_float2(sigmoidf_((acc[nt][2] + bs0) * inv),
                                sigmoidf_((acc[nt][3] + bs1) * inv));
        *reinterpret_cast<float2*>(&out[(size_t)row0 * OUTDIM + col])       = r0;
        *reinterpret_cast<float2*>(&out[(size_t)(row0 + 8) * OUTDIM + col]) = r1;
    }
}

// ---------------------------------------------------------------------------
extern "C" void kernel_launch(void* const* d_in, const int* in_sizes, int n_in,
                              void* d_out, int out_size) {
    const float* x    = (const float*)d_in[0];
    const float* wgt  = (const float*)d_in[1];
    const float* bias = (const float*)d_in[2];
    float* out        = (float*)d_out;
    (void)in_sizes; (void)n_in; (void)out_size;

    // attribute set (idempotent; not a stream op, not an allocation)
    cudaFuncSetAttribute(gemm_kernel,
                         cudaFuncAttributeMaxDynamicSharedMemorySize, SMEM_TOTAL);

    prep_kernel<<<768, 256>>>(x, wgt, bias);

    dim3 g(OUTDIM / BN, BATCH / BM);   // (16, 8) = 128 CTAs
    gemm_kernel<<<g, 256, SMEM_TOTAL>>>(out);
}